// round 7
// baseline (speedup 1.0000x reference)
#include <cuda_runtime.h>
#include <math.h>

#define B_  8
#define T_  256
#define U_  64
#define U1_ 65
#define V_  512
#define S_  66                         // padded row stride (2-way conflict max)

#define ROWS (B_ * T_ * U1_)           // 133120

__device__ float g_blank[ROWS];
__device__ float g_emit[ROWS];
__device__ float g_partial[B_];

// ---------------------------------------------------------------------------
// Kernel 1: per-row log-softmax; extract blank (v=0) and emit (v=target) only.
// One warp per (b,t,u) row; single pass, registers only.  ~HBM roofline.
// ---------------------------------------------------------------------------
__global__ void __launch_bounds__(256) lse_kernel(const float* __restrict__ pred,
                                                  const int* __restrict__ target) {
    const int row  = blockIdx.x * 8 + (threadIdx.x >> 5);
    const int lane = threadIdx.x & 31;
    if (row >= ROWS) return;

    const float4* p = (const float4*)(pred + (size_t)row * V_);
    float4 r[4];
#pragma unroll
    for (int k = 0; k < 4; k++) r[k] = p[k * 32 + lane];

    float m = fmaxf(fmaxf(r[0].x, r[0].y), fmaxf(r[0].z, r[0].w));
#pragma unroll
    for (int k = 1; k < 4; k++)
        m = fmaxf(m, fmaxf(fmaxf(r[k].x, r[k].y), fmaxf(r[k].z, r[k].w)));
#pragma unroll
    for (int o = 16; o > 0; o >>= 1)
        m = fmaxf(m, __shfl_xor_sync(0xffffffffu, m, o));

    float s = 0.f;
#pragma unroll
    for (int k = 0; k < 4; k++)
        s += __expf(r[k].x - m) + __expf(r[k].y - m) +
             __expf(r[k].z - m) + __expf(r[k].w - m);
#pragma unroll
    for (int o = 16; o > 0; o >>= 1)
        s += __shfl_xor_sync(0xffffffffu, s, o);

    const float lse = m + __logf(s);

    const int u = row % U1_;
    const int b = row / (T_ * U1_);

    if (lane == 0) g_blank[row] = r[0].x - lse;

    if (u < U_) {
        const int tgt = target[b * U_ + u];
        float e = 0.f;
        bool have = false;
#pragma unroll
        for (int k = 0; k < 4; k++) {
            const int base = (k * 32 + lane) << 2;
            if (tgt >= base && tgt < base + 4) {
                have = true;
                if (tgt == base)     e = r[k].x;
                if (tgt == base + 1) e = r[k].y;
                if (tgt == base + 2) e = r[k].z;
                if (tgt == base + 3) e = r[k].w;
            }
        }
        if (have) g_emit[row] = e - lse;
    }
}

// ---------------------------------------------------------------------------
// Kernel 2: single-warp wavefront DP per batch. Lane l owns u = {2l, 2l+1};
// lane 31 additionally owns u = 64. Cross-lane dep = one shfl_up per step.
// NO __syncthreads in the 320-step main loop.
// ---------------------------------------------------------------------------
__device__ __forceinline__ float lae(float a, float b) {
    const float mx = fmaxf(a, b);
    const float d  = -fabsf(a - b);
    return mx + __logf(1.f + __expf(d));
}

__global__ void __launch_bounds__(128) dp_kernel(const int* __restrict__ pred_len,
                                                 const int* __restrict__ target_len) {
    const int b = blockIdx.x;

    extern __shared__ float sm[];
    float* sb = sm;                    // blank  [T_][S_]
    float* se = sm + T_ * S_;          // emit   [T_][S_]

    // Stage tables with all 4 warps (coalesced from L2).
    const float* gb = g_blank + b * T_ * U1_;
    const float* ge = g_emit  + b * T_ * U1_;
    for (int i = threadIdx.x; i < T_ * U1_; i += 128) {
        const int t  = i / U1_;
        const int uu = i - t * U1_;
        sb[t * S_ + uu] = gb[i];
        se[t * S_ + uu] = ge[i];
    }
    __syncthreads();
    if (threadIdx.x >= 32) return;

    const int l  = threadIdx.x;
    const int u0 = 2 * l;
    const int u1 = 2 * l + 1;
    const bool lane31 = (l == 31);

    const int plast = pred_len[b] - 1;
    const int tlen  = target_len[b];

    float a0 = 0.f, a1 = 0.f, a2 = 0.f;

#pragma unroll 4
    for (int n = 0; n < T_ + U_; n++) {
        const int t0 = n - u0;
        const int t1 = n - u1;
        const int t2 = n - 64;

        // Clamped, unconditional SMEM loads — addresses depend only on n,
        // so they issue before the shfl resolves (off the critical path).
        const int tb0 = min(max(t0, 1), T_ - 1);
        const int tb1 = min(max(t1, 1), T_ - 1);
        const int tb2 = min(max(t2, 1), T_ - 1);
        const int te0 = min(max(t0, 0), T_ - 1);
        const int te1 = min(max(t1, 0), T_ - 1);
        const int te2 = min(max(t2, 0), T_ - 1);
        const float bl0 = sb[(tb0 - 1) * S_ + u0];
        const float bl1 = sb[(tb1 - 1) * S_ + u1];
        const float bl2 = sb[(tb2 - 1) * S_ + 64];
        const float em0 = (u0 > 0) ? se[te0 * S_ + (u0 - 1)] : 0.f;
        const float em1 = se[te1 * S_ + (u1 - 1)];
        const float em2 = se[te2 * S_ + 63];

        // Previous-step neighbor values.
        const float left0 = __shfl_up_sync(0xffffffffu, a1, 1); // alpha[t0][u0-1]
        const float left1 = a0;                                  // alpha[t1][u1-1]
        const float left2 = a1;                                  // alpha[t2][63]

        if (t0 >= 0 && t0 < T_) {
            float v;
            if (t0 == 0)       v = (u0 == 0) ? 0.f : left0 + em0;  // row0 cumsum
            else if (u0 == 0)  v = a0 + bl0;
            else               v = lae(a0 + bl0, left0 + em0);
            if (t0 == plast && u0 == tlen)
                g_partial[b] = -(v + sb[plast * S_ + tlen]);
            a0 = v;
        }
        if (t1 >= 0 && t1 < T_) {
            float v;
            if (t1 == 0)       v = left1 + em1;
            else               v = lae(a1 + bl1, left1 + em1);
            if (t1 == plast && u1 == tlen)
                g_partial[b] = -(v + sb[plast * S_ + tlen]);
            a1 = v;
        }
        if (lane31 && t2 >= 0 && t2 < T_) {
            float v;
            if (t2 == 0)       v = left2 + em2;
            else               v = lae(a2 + bl2, left2 + em2);
            if (t2 == plast && 64 == tlen)
                g_partial[b] = -(v + sb[plast * S_ + 64]);
            a2 = v;
        }
    }
}

// ---------------------------------------------------------------------------
// Kernel 3: mean over batch -> d_out[0]
// ---------------------------------------------------------------------------
__global__ void finish_kernel(float* __restrict__ out) {
    if (threadIdx.x == 0) {
        float s = 0.f;
#pragma unroll
        for (int i = 0; i < B_; i++) s += g_partial[i];
        out[0] = s * (1.f / B_);
    }
}

extern "C" void kernel_launch(void* const* d_in, const int* in_sizes, int n_in,
                              void* d_out, int out_size) {
    const float* pred       = (const float*)d_in[0];
    const int*   target     = (const int*)d_in[1];
    const int*   pred_len   = (const int*)d_in[2];
    const int*   target_len = (const int*)d_in[3];
    float*       out        = (float*)d_out;

    const int smem_bytes = 2 * T_ * S_ * (int)sizeof(float);

    static bool attr_done = false;
    if (!attr_done) {
        cudaFuncSetAttribute(dp_kernel, cudaFuncAttributeMaxDynamicSharedMemorySize, smem_bytes);
        attr_done = true;
    }

    lse_kernel<<<ROWS / 8, 256>>>(pred, target);
    dp_kernel<<<B_, 128, smem_bytes>>>(pred_len, target_len);
    finish_kernel<<<1, 32>>>(out);
}